// round 14
// baseline (speedup 1.0000x reference)
#include <cuda_runtime.h>
#include <math.h>
#include <stdint.h>

#define NN 50000
#define EE 800000
#define IN_DIM 128
#define HD 128
#define HD2 64
#define OUT_DIM 1000
#define KHOPS 10
#define EPSV 1e-5f
#define HOPCHUNKS (NN * 16 / 256)   // 3125 dst-group chunks per hop

// ---------------- scratch (device globals; no allocation allowed) ------------
__device__ float g_Y1[(size_t)NN * HD];    // pre-BN layer 1
__device__ float g_Y2[(size_t)NN * HD];    // pre-BN layer 2
__device__ float g_P[(size_t)NN * HD2];    // projected 64d (read every Horner step)
__device__ float g_PB[(size_t)NN * HD2];   // Horner ping (starts = w10*P; final result)
__device__ float g_QB[(size_t)NN * HD2];   // Horner pong
__device__ float g_S1[HD], g_Q1[HD], g_S2[HD], g_Q2[HD], g_S3[HD2], g_Q3[HD2];
__device__ float g_w[KHOPS + 1];
__device__ int   g_deg[NN];
__device__ int   g_rowptr[NN + 1];
__device__ int   g_cursor[NN];
__device__ int   g_colidx[EE];
__device__ int   g_bar_count;
__device__ int   g_bar_gen;

// ---------------- init: zero stats/degrees/barrier, softmax(att) -------------
__global__ void k_init(const float* __restrict__ att) {
    int t = blockIdx.x * blockDim.x + threadIdx.x;
    int stride = gridDim.x * blockDim.x;
    for (int i = t; i < NN; i += stride) g_deg[i] = 0;
    if (t < HD)  { g_S1[t] = 0.f; g_Q1[t] = 0.f; g_S2[t] = 0.f; g_Q2[t] = 0.f; }
    if (t < HD2) { g_S3[t] = 0.f; g_Q3[t] = 0.f; }
    if (t == 0) {
        g_bar_count = 0;
        g_bar_gen = 0;
        float m = -1e30f;
        for (int i = 0; i <= KHOPS; i++) m = fmaxf(m, att[i]);
        float e[KHOPS + 1]; float s = 0.f;
        for (int i = 0; i <= KHOPS; i++) { e[i] = expf(att[i] - m); s += e[i]; }
        for (int i = 0; i <= KHOPS; i++) g_w[i] = e[i] / s;
    }
}

// ---------------- FFMA tiled GEMM: C = act(A)[M,K] @ B[K,Nc] -----------------
// BM=128, BN=64, BK=16, 256 threads, 8x4 register tile (proven R4 config).
//   FUSEA : A_eff[r,k]  = relu(A[r,k]*aScale[k] + aShift[k])
//   RESID2: A_eff[r,k] += relu(R[r,k]*rScale[k] + rShift[k])
//   STATS : fused BN column stats on C (Sp/Qp).
//   DUAL  : also write C2 = g_w[KHOPS] * C  (Horner seed t10 = w10*P).
template<bool FUSEA, bool RESID2, bool STATS, bool DUAL>
__global__ __launch_bounds__(256, 2)
void k_gemm(const float* __restrict__ A, const float* __restrict__ B,
            float* __restrict__ C, float* __restrict__ C2,
            float* __restrict__ Sp, float* __restrict__ Qp,
            const float* __restrict__ gA, const float* __restrict__ beA,
            const float* __restrict__ SA, const float* __restrict__ QA,
            const float* __restrict__ R,
            const float* __restrict__ gR, const float* __restrict__ beR,
            const float* __restrict__ SR, const float* __restrict__ QR,
            int M, int Nc, int K) {
    __shared__ float As[128][17];
    __shared__ float Bs[16][68];
    __shared__ float cS[64], cQ[64];
    __shared__ float aSc[128], aSh[128], rSc[128], rSh[128];
    int tid = threadIdx.x;
    int tx = tid & 15;
    int ty = tid >> 4;
    int rowBase = blockIdx.y * 128;
    int colBase = blockIdx.x * 64;
    float acc[8][4] = {};

    if (STATS && tid < 64) { cS[tid] = 0.f; cQ[tid] = 0.f; }
    if (FUSEA && tid < K) {
        float mean = SA[tid] / (float)M;
        float var = QA[tid] / (float)M - mean * mean;
        float scale = gA[tid] * rsqrtf(var + EPSV);
        aSc[tid] = scale;
        aSh[tid] = beA[tid] - mean * scale;
    }
    if (RESID2 && tid < K) {
        float mean = SR[tid] / (float)M;
        float var = QR[tid] / (float)M - mean * mean;
        float scale = gR[tid] * rsqrtf(var + EPSV);
        rSc[tid] = scale;
        rSh[tid] = beR[tid] - mean * scale;
    }
    if (FUSEA || RESID2) __syncthreads();

    for (int k0 = 0; k0 < K; k0 += 16) {
        #pragma unroll
        for (int l = 0; l < 2; l++) {
            int f = tid + l * 256;
            int r = f >> 2, c = (f & 3) * 4;
            int gr = rowBase + r;
            float4 v = make_float4(0.f, 0.f, 0.f, 0.f);
            if (gr < M) {
                v = *(const float4*)(A + (size_t)gr * K + k0 + c);
                if (FUSEA) {
                    int kc = k0 + c;
                    v.x = fmaxf(fmaf(v.x, aSc[kc + 0], aSh[kc + 0]), 0.f);
                    v.y = fmaxf(fmaf(v.y, aSc[kc + 1], aSh[kc + 1]), 0.f);
                    v.z = fmaxf(fmaf(v.z, aSc[kc + 2], aSh[kc + 2]), 0.f);
                    v.w = fmaxf(fmaf(v.w, aSc[kc + 3], aSh[kc + 3]), 0.f);
                }
                if (RESID2) {
                    int kc = k0 + c;
                    float4 rr = *(const float4*)(R + (size_t)gr * K + k0 + c);
                    v.x += fmaxf(fmaf(rr.x, rSc[kc + 0], rSh[kc + 0]), 0.f);
                    v.y += fmaxf(fmaf(rr.y, rSc[kc + 1], rSh[kc + 1]), 0.f);
                    v.z += fmaxf(fmaf(rr.z, rSc[kc + 2], rSh[kc + 2]), 0.f);
                    v.w += fmaxf(fmaf(rr.w, rSc[kc + 3], rSh[kc + 3]), 0.f);
                }
            }
            As[r][c] = v.x; As[r][c + 1] = v.y; As[r][c + 2] = v.z; As[r][c + 3] = v.w;
        }
        {
            int r = tid >> 4, c = (tid & 15) * 4;
            int gc = colBase + c;
            float4 v = make_float4(0.f, 0.f, 0.f, 0.f);
            if (gc < Nc) v = *(const float4*)(B + (size_t)(k0 + r) * Nc + gc);
            Bs[r][c] = v.x; Bs[r][c + 1] = v.y; Bs[r][c + 2] = v.z; Bs[r][c + 3] = v.w;
        }
        __syncthreads();
        #pragma unroll
        for (int kk = 0; kk < 16; kk++) {
            float4 bv = *(const float4*)&Bs[kk][tx * 4];
            float a[8];
            #pragma unroll
            for (int i = 0; i < 8; i++) a[i] = As[ty * 8 + i][kk];
            #pragma unroll
            for (int i = 0; i < 8; i++) {
                acc[i][0] = fmaf(a[i], bv.x, acc[i][0]);
                acc[i][1] = fmaf(a[i], bv.y, acc[i][1]);
                acc[i][2] = fmaf(a[i], bv.z, acc[i][2]);
                acc[i][3] = fmaf(a[i], bv.w, acc[i][3]);
            }
        }
        __syncthreads();
    }
    float w10 = DUAL ? g_w[KHOPS] : 0.f;
    #pragma unroll
    for (int i = 0; i < 8; i++) {
        int r = rowBase + ty * 8 + i;
        if (r >= M) continue;
        #pragma unroll
        for (int j = 0; j < 4; j++) {
            int c = colBase + tx * 4 + j;
            if (c < Nc) {
                float v = acc[i][j];
                C[(size_t)r * Nc + c] = v;
                if (DUAL) C2[(size_t)r * Nc + c] = w10 * v;
            }
        }
    }
    if (STATS) {
        float s[4] = {0.f, 0.f, 0.f, 0.f};
        float q[4] = {0.f, 0.f, 0.f, 0.f};
        #pragma unroll
        for (int i = 0; i < 8; i++) {
            int r = rowBase + ty * 8 + i;
            if (r >= M) continue;
            #pragma unroll
            for (int j = 0; j < 4; j++) {
                float v = acc[i][j];
                s[j] += v; q[j] += v * v;
            }
        }
        #pragma unroll
        for (int j = 0; j < 4; j++) {
            atomicAdd(&cS[tx * 4 + j], s[j]);
            atomicAdd(&cQ[tx * 4 + j], q[j]);
        }
        __syncthreads();
        if (tid < 64) {
            int c = colBase + tid;
            if (c < Nc) {
                atomicAdd(Sp + c, cS[tid]);
                atomicAdd(Qp + c, cQ[tid]);
            }
        }
    }
}

// ---------------- tf32 helpers -----------------------------------------------
__device__ __forceinline__ uint32_t f2tf32(float f) {
    uint32_t r;
    asm("cvt.rna.tf32.f32 %0, %1;" : "=r"(r) : "f"(f));
    return r;
}
__device__ __forceinline__ void mma_tf32(float* c, const uint32_t* a, const uint32_t* b) {
    asm("mma.sync.aligned.m16n8k8.row.col.f32.tf32.tf32.f32 "
        "{%0,%1,%2,%3}, {%4,%5,%6,%7}, {%8,%9}, {%0,%1,%2,%3};"
        : "+f"(c[0]), "+f"(c[1]), "+f"(c[2]), "+f"(c[3])
        : "r"(a[0]), "r"(a[1]), "r"(a[2]), "r"(a[3]), "r"(b[0]), "r"(b[1]));
}

// ---------------- tf32 tensor-core output GEMM (1x, K=64) --------------------
__global__ __launch_bounds__(256, 2)
void k_gemm_tc(const float* __restrict__ A, const float* __restrict__ B,
               const float* __restrict__ bias, float* __restrict__ C,
               const float* __restrict__ gA, const float* __restrict__ beA,
               const float* __restrict__ SA, const float* __restrict__ QA,
               int M, int Nc) {
    __shared__ float As[128][68];
    __shared__ float Bs[64][132];
    __shared__ float aSc[HD2], aSh[HD2];
    int tid = threadIdx.x;
    int rowBase = blockIdx.y * 128;
    int colBase = blockIdx.x * 128;

    if (tid < HD2) {
        float mean = SA[tid] / (float)M;
        float var = QA[tid] / (float)M - mean * mean;
        float scale = gA[tid] * rsqrtf(var + EPSV);
        aSc[tid] = scale;
        aSh[tid] = beA[tid] - mean * scale;
    }
    __syncthreads();

    #pragma unroll
    for (int l = 0; l < 8; l++) {
        int f = tid + l * 256;
        int r = f >> 4;
        int c = (f & 15) * 4;
        int gr = rowBase + r;
        float4 v = make_float4(0.f, 0.f, 0.f, 0.f);
        if (gr < M) {
            v = *(const float4*)(A + (size_t)gr * HD2 + c);
            v.x = fmaxf(fmaf(v.x, aSc[c + 0], aSh[c + 0]), 0.f);
            v.y = fmaxf(fmaf(v.y, aSc[c + 1], aSh[c + 1]), 0.f);
            v.z = fmaxf(fmaf(v.z, aSc[c + 2], aSh[c + 2]), 0.f);
            v.w = fmaxf(fmaf(v.w, aSc[c + 3], aSh[c + 3]), 0.f);
        }
        As[r][c] = v.x; As[r][c + 1] = v.y; As[r][c + 2] = v.z; As[r][c + 3] = v.w;
    }
    #pragma unroll
    for (int l = 0; l < 8; l++) {
        int f = tid + l * 256;
        int r = f >> 5;
        int c = (f & 31) * 4;
        int gc = colBase + c;
        float4 v = make_float4(0.f, 0.f, 0.f, 0.f);
        if (gc + 3 < Nc) v = *(const float4*)(B + (size_t)r * Nc + gc);
        Bs[r][c] = v.x; Bs[r][c + 1] = v.y; Bs[r][c + 2] = v.z; Bs[r][c + 3] = v.w;
    }
    __syncthreads();

    int warpId = tid >> 5;
    int lane = tid & 31;
    int g = lane >> 2;
    int t = lane & 3;
    int rowOff = (warpId >> 2) * 64;
    int colOff = (warpId & 3) * 32;

    float cacc[4][4][4] = {};

    #pragma unroll
    for (int ks = 0; ks < 8; ks++) {
        int kb = ks * 8;
        uint32_t af[4][4];
        #pragma unroll
        for (int mt = 0; mt < 4; mt++) {
            int r0 = rowOff + mt * 16 + g;
            af[mt][0] = f2tf32(As[r0][kb + t]);
            af[mt][1] = f2tf32(As[r0 + 8][kb + t]);
            af[mt][2] = f2tf32(As[r0][kb + t + 4]);
            af[mt][3] = f2tf32(As[r0 + 8][kb + t + 4]);
        }
        uint32_t bf[4][2];
        #pragma unroll
        for (int nt = 0; nt < 4; nt++) {
            int c0 = colOff + nt * 8 + g;
            bf[nt][0] = f2tf32(Bs[kb + t][c0]);
            bf[nt][1] = f2tf32(Bs[kb + t + 4][c0]);
        }
        #pragma unroll
        for (int mt = 0; mt < 4; mt++)
            #pragma unroll
            for (int nt = 0; nt < 4; nt++)
                mma_tf32(cacc[mt][nt], af[mt], bf[nt]);
    }

    #pragma unroll
    for (int mt = 0; mt < 4; mt++) {
        int row0 = rowBase + rowOff + mt * 16 + g;
        int row1 = row0 + 8;
        #pragma unroll
        for (int nt = 0; nt < 4; nt++) {
            int col = colBase + colOff + nt * 8 + 2 * t;
            const float* cc = cacc[mt][nt];
            if (row0 < M) {
                if (col < Nc)     C[(size_t)row0 * Nc + col]     = cc[0] + bias[col];
                if (col + 1 < Nc) C[(size_t)row0 * Nc + col + 1] = cc[1] + bias[col + 1];
            }
            if (row1 < M) {
                if (col < Nc)     C[(size_t)row1 * Nc + col]     = cc[2] + bias[col];
                if (col + 1 < Nc) C[(size_t)row1 * Nc + col + 1] = cc[3] + bias[col + 1];
            }
        }
    }
}

// ---------------- CSR build: histogram -> scan -> scatter --------------------
__global__ void k_hist(const int* __restrict__ dst) {
    int t = blockIdx.x * blockDim.x + threadIdx.x;
    int stride = gridDim.x * blockDim.x;
    for (int e = t; e < EE; e += stride) atomicAdd(&g_deg[dst[e]], 1);
}

__global__ void k_scan() {  // one block, 1024 threads
    __shared__ int ss[1024];
    int t = threadIdx.x;
    const int CH = (NN + 1023) / 1024;
    int lo = t * CH;
    int hi = lo + CH; if (hi > NN) hi = NN;
    int loc = 0;
    for (int i = lo; i < hi; i++) loc += g_deg[i];
    ss[t] = loc;
    __syncthreads();
    for (int off = 1; off < 1024; off <<= 1) {
        int v = (t >= off) ? ss[t - off] : 0;
        __syncthreads();
        ss[t] += v;
        __syncthreads();
    }
    int run = ss[t] - loc;  // exclusive prefix
    for (int i = lo; i < hi; i++) {
        g_rowptr[i] = run;
        g_cursor[i] = run;
        run += g_deg[i];
    }
    if (t == 1023) g_rowptr[NN] = ss[1023];
}

__global__ void k_scatter(const int* __restrict__ src, const int* __restrict__ dst) {
    int t = blockIdx.x * blockDim.x + threadIdx.x;
    int stride = gridDim.x * blockDim.x;
    for (int e = t; e < EE; e += stride) {
        int d = dst[e];
        int p = atomicAdd(&g_cursor[d], 1);
        g_colidx[p] = src[e];
    }
}

// ---------------- software grid barrier (all blocks co-resident) -------------
__device__ __forceinline__ void grid_barrier(int nblocks) {
    __threadfence();
    __syncthreads();
    if (threadIdx.x == 0) {
        int gen = atomicAdd(&g_bar_gen, 0);
        if (atomicAdd(&g_bar_count, 1) == nblocks - 1) {
            g_bar_count = 0;
            __threadfence();
            atomicExch(&g_bar_gen, gen + 1);
        } else {
            while (atomicAdd(&g_bar_gen, 0) == gen) __nanosleep(64);
        }
        __threadfence();
    }
    __syncthreads();
}

// ---------------- persistent Horner propagation ------------------------------
// All 10 steps in one launch. Step k: nxt[d] = w[k]*P[d] + sum_in cur[src].
// k=9..0; cur = (k odd ? PB : QB); final (k=0) lands in PB and fuses BN3 stats.
// Grid must be <= resident capacity (host sizes it via the occupancy API).
__global__ __launch_bounds__(256)
void k_hops_persist(int nblocks) {
    __shared__ float sS[64], sQ[64];
    int tid = threadIdx.x;
    if (tid < 64) { sS[tid] = 0.f; sQ[tid] = 0.f; }

    for (int k = KHOPS - 1; k >= 0; k--) {
        const float* __restrict__ cur = (k & 1) ? g_PB : g_QB;
        float* __restrict__ nxt       = (k & 1) ? g_QB : g_PB;
        float wk = g_w[k];
        bool last = (k == 0);

        for (int blk = blockIdx.x; blk < HOPCHUNKS; blk += gridDim.x) {
            int gid = blk * 256 + tid;
            int d = gid >> 4;            // half-warp per destination node
            int lane = tid & 15;
            int s = g_rowptr[d];
            int e = g_rowptr[d + 1];
            float4 acc0 = make_float4(0.f, 0.f, 0.f, 0.f);
            float4 acc1 = make_float4(0.f, 0.f, 0.f, 0.f);
            float4 acc2 = make_float4(0.f, 0.f, 0.f, 0.f);
            float4 acc3 = make_float4(0.f, 0.f, 0.f, 0.f);
            int i = s;
            for (; i + 3 < e; i += 4) {
                int s0 = __ldg(&g_colidx[i]);
                int s1 = __ldg(&g_colidx[i + 1]);
                int s2 = __ldg(&g_colidx[i + 2]);
                int s3 = __ldg(&g_colidx[i + 3]);
                float4 v0 = *(const float4*)(cur + (size_t)s0 * HD2 + lane * 4);
                float4 v1 = *(const float4*)(cur + (size_t)s1 * HD2 + lane * 4);
                float4 v2 = *(const float4*)(cur + (size_t)s2 * HD2 + lane * 4);
                float4 v3 = *(const float4*)(cur + (size_t)s3 * HD2 + lane * 4);
                acc0.x += v0.x; acc0.y += v0.y; acc0.z += v0.z; acc0.w += v0.w;
                acc1.x += v1.x; acc1.y += v1.y; acc1.z += v1.z; acc1.w += v1.w;
                acc2.x += v2.x; acc2.y += v2.y; acc2.z += v2.z; acc2.w += v2.w;
                acc3.x += v3.x; acc3.y += v3.y; acc3.z += v3.z; acc3.w += v3.w;
            }
            for (; i < e; i++) {
                int s0 = __ldg(&g_colidx[i]);
                float4 v0 = *(const float4*)(cur + (size_t)s0 * HD2 + lane * 4);
                acc0.x += v0.x; acc0.y += v0.y; acc0.z += v0.z; acc0.w += v0.w;
            }
            float4 a = make_float4((acc0.x + acc1.x) + (acc2.x + acc3.x),
                                   (acc0.y + acc1.y) + (acc2.y + acc3.y),
                                   (acc0.z + acc1.z) + (acc2.z + acc3.z),
                                   (acc0.w + acc1.w) + (acc2.w + acc3.w));
            size_t base = (size_t)d * HD2 + lane * 4;
            float4 p = *(const float4*)(g_P + base);
            float4 q;
            q.x = fmaf(wk, p.x, a.x);
            q.y = fmaf(wk, p.y, a.y);
            q.z = fmaf(wk, p.z, a.z);
            q.w = fmaf(wk, p.w, a.w);
            *(float4*)(nxt + base) = q;

            if (last) {
                float s0 = q.x, s1 = q.y, s2 = q.z, s3 = q.w;
                float q0 = q.x * q.x, q1 = q.y * q.y, q2 = q.z * q.z, q3 = q.w * q.w;
                s0 += __shfl_xor_sync(0xFFFFFFFF, s0, 16);
                s1 += __shfl_xor_sync(0xFFFFFFFF, s1, 16);
                s2 += __shfl_xor_sync(0xFFFFFFFF, s2, 16);
                s3 += __shfl_xor_sync(0xFFFFFFFF, s3, 16);
                q0 += __shfl_xor_sync(0xFFFFFFFF, q0, 16);
                q1 += __shfl_xor_sync(0xFFFFFFFF, q1, 16);
                q2 += __shfl_xor_sync(0xFFFFFFFF, q2, 16);
                q3 += __shfl_xor_sync(0xFFFFFFFF, q3, 16);
                if ((tid & 31) < 16) {
                    int c0 = lane * 4;
                    atomicAdd(&sS[c0 + 0], s0); atomicAdd(&sQ[c0 + 0], q0);
                    atomicAdd(&sS[c0 + 1], s1); atomicAdd(&sQ[c0 + 1], q1);
                    atomicAdd(&sS[c0 + 2], s2); atomicAdd(&sQ[c0 + 2], q2);
                    atomicAdd(&sS[c0 + 3], s3); atomicAdd(&sQ[c0 + 3], q3);
                }
            }
        }
        if (k > 0) grid_barrier(nblocks);
    }
    __syncthreads();
    if (tid < 64) {
        atomicAdd(g_S3 + tid, sS[tid]);
        atomicAdd(g_Q3 + tid, sQ[tid]);
    }
}

// ---------------- host launcher ----------------------------------------------
extern "C" void kernel_launch(void* const* d_in, const int* in_sizes, int n_in,
                              void* d_out, int out_size) {
    const float* x    = (const float*)d_in[0];
    const int*   ei   = (const int*)d_in[1];
    const float* W1   = (const float*)d_in[2];
    const float* g1   = (const float*)d_in[4];
    const float* be1  = (const float*)d_in[5];
    const float* W2   = (const float*)d_in[6];
    const float* g2   = (const float*)d_in[8];
    const float* be2  = (const float*)d_in[9];
    const float* att  = (const float*)d_in[10];
    const float* W3   = (const float*)d_in[11];
    const float* g3   = (const float*)d_in[13];
    const float* be3  = (const float*)d_in[14];
    const float* Wout = (const float*)d_in[15];
    const float* bout = (const float*)d_in[16];
    const int* srcp = ei;
    const int* dstp = ei + EE;
    float* out = (float*)d_out;

    float *Y1, *Y2, *P, *PB, *S1, *Q1, *S2, *Q2, *S3, *Q3;
    cudaGetSymbolAddress((void**)&Y1, g_Y1);
    cudaGetSymbolAddress((void**)&Y2, g_Y2);
    cudaGetSymbolAddress((void**)&P,  g_P);
    cudaGetSymbolAddress((void**)&PB, g_PB);
    cudaGetSymbolAddress((void**)&S1, g_S1);
    cudaGetSymbolAddress((void**)&Q1, g_Q1);
    cudaGetSymbolAddress((void**)&S2, g_S2);
    cudaGetSymbolAddress((void**)&Q2, g_Q2);
    cudaGetSymbolAddress((void**)&S3, g_S3);
    cudaGetSymbolAddress((void**)&Q3, g_Q3);

    const int MB = (NN + 127) / 128;  // 391 row-tiles

    // persistent-hop grid: guaranteed co-resident (occupancy query, host-side only)
    int dev = 0, nsm = 148, perSM = 0;
    cudaGetDevice(&dev);
    cudaDeviceGetAttribute(&nsm, cudaDevAttrMultiProcessorCount, dev);
    cudaOccupancyMaxActiveBlocksPerMultiprocessor(&perSM, k_hops_persist, 256, 0);
    if (perSM < 1) perSM = 1;
    int hopGrid = nsm * perSM;
    if (hopGrid > HOPCHUNKS) hopGrid = HOPCHUNKS;

    k_init<<<200, 256>>>(att);

    // CSR by destination (independent of MLP; do it early)
    k_hist<<<1024, 256>>>(dstp);
    k_scan<<<1, 1024>>>();
    k_scatter<<<1024, 256>>>(srcp, dstp);

    // layer 1: Y1 = x @ W1 (stats fused), FFMA
    k_gemm<false, false, true, false><<<dim3(2, MB), 256>>>(
        x, W1, Y1, nullptr, S1, Q1,
        nullptr, nullptr, nullptr, nullptr,
        nullptr, nullptr, nullptr, nullptr, nullptr, NN, HD, IN_DIM);

    // layer 2: Y2 = relu(bn1(Y1)) @ W2 (apply fused on A; stats fused), FFMA
    k_gemm<true, false, true, false><<<dim3(2, MB), 256>>>(
        Y1, W2, Y2, nullptr, S2, Q2,
        g1, be1, S1, Q1,
        nullptr, nullptr, nullptr, nullptr, nullptr, NN, HD, HD);

    // projection: P = (relu(bn2(Y2)) + relu(bn1(Y1))) @ W3;  PB = w10 * P (Horner seed)
    k_gemm<true, true, false, true><<<dim3(1, MB), 256>>>(
        Y2, W3, P, PB, nullptr, nullptr,
        g2, be2, S2, Q2,
        Y1, g1, be1, S1, Q1, NN, HD2, HD);

    // persistent Horner: all 10 hops + fused BN3 stats, one launch
    k_hops_persist<<<hopGrid, 256>>>(hopGrid);

    // output: out = relu(bn3(t0)) @ Wout + bout   [1x tf32 tensor cores]
    k_gemm_tc<<<dim3((OUT_DIM + 127) / 128, MB), 256>>>(
        PB, Wout, bout, out, g3, be3, S3, Q3, NN, OUT_DIM);
}

// round 15
// speedup vs baseline: 1.2419x; 1.2419x over previous
#include <cuda_runtime.h>
#include <math.h>
#include <stdint.h>

#define NN 50000
#define EE 800000
#define IN_DIM 128
#define HD 128
#define HD2 64
#define OUT_DIM 1000
#define KHOPS 10
#define EPSV 1e-5f

// ---------------- scratch (device globals; no allocation allowed) ------------
__device__ float g_Y1[(size_t)NN * HD];    // pre-BN layer 1
__device__ float g_Y2[(size_t)NN * HD];    // pre-BN layer 2
__device__ float g_P[(size_t)NN * HD2];    // projected 64d (read every Horner step)
__device__ float g_PB[(size_t)NN * HD2];   // Horner ping (starts = w10*P; final result)
__device__ float g_QB[(size_t)NN * HD2];   // Horner pong
__device__ float g_S1[HD], g_Q1[HD], g_S2[HD], g_Q2[HD], g_S3[HD2], g_Q3[HD2];
__device__ float g_w[KHOPS + 1];
__device__ int   g_deg[NN];
__device__ int   g_rowptr[NN + 1];
__device__ int   g_cursor[NN];
__device__ int   g_colidx[EE];

// ---------------- init: zero stats/degrees, softmax(att) ---------------------
__global__ void k_init(const float* __restrict__ att) {
    int t = blockIdx.x * blockDim.x + threadIdx.x;
    int stride = gridDim.x * blockDim.x;
    for (int i = t; i < NN; i += stride) g_deg[i] = 0;
    if (t < HD)  { g_S1[t] = 0.f; g_Q1[t] = 0.f; g_S2[t] = 0.f; g_Q2[t] = 0.f; }
    if (t < HD2) { g_S3[t] = 0.f; g_Q3[t] = 0.f; }
    if (t == 0) {
        float m = -1e30f;
        for (int i = 0; i <= KHOPS; i++) m = fmaxf(m, att[i]);
        float e[KHOPS + 1]; float s = 0.f;
        for (int i = 0; i <= KHOPS; i++) { e[i] = expf(att[i] - m); s += e[i]; }
        for (int i = 0; i <= KHOPS; i++) g_w[i] = e[i] / s;
    }
}

// ---------------- FFMA tiled GEMM: C = act(A)[M,K] @ B[K,Nc] -----------------
// BM=128, BN=64, BK=16, 256 threads, 8x4 register tile (proven R4 config).
//   FUSEA : A_eff[r,k]  = relu(A[r,k]*aScale[k] + aShift[k])
//   RESID2: A_eff[r,k] += relu(R[r,k]*rScale[k] + rShift[k])
//   STATS : fused BN column stats on C (Sp/Qp).
//   DUAL  : also write C2 = g_w[KHOPS] * C  (Horner seed t10 = w10*P).
template<bool FUSEA, bool RESID2, bool STATS, bool DUAL>
__global__ __launch_bounds__(256, 2)
void k_gemm(const float* __restrict__ A, const float* __restrict__ B,
            float* __restrict__ C, float* __restrict__ C2,
            float* __restrict__ Sp, float* __restrict__ Qp,
            const float* __restrict__ gA, const float* __restrict__ beA,
            const float* __restrict__ SA, const float* __restrict__ QA,
            const float* __restrict__ R,
            const float* __restrict__ gR, const float* __restrict__ beR,
            const float* __restrict__ SR, const float* __restrict__ QR,
            int M, int Nc, int K) {
    __shared__ float As[128][17];
    __shared__ float Bs[16][68];
    __shared__ float cS[64], cQ[64];
    __shared__ float aSc[128], aSh[128], rSc[128], rSh[128];
    int tid = threadIdx.x;
    int tx = tid & 15;
    int ty = tid >> 4;
    int rowBase = blockIdx.y * 128;
    int colBase = blockIdx.x * 64;
    float acc[8][4] = {};

    if (STATS && tid < 64) { cS[tid] = 0.f; cQ[tid] = 0.f; }
    if (FUSEA && tid < K) {
        float mean = SA[tid] / (float)M;
        float var = QA[tid] / (float)M - mean * mean;
        float scale = gA[tid] * rsqrtf(var + EPSV);
        aSc[tid] = scale;
        aSh[tid] = beA[tid] - mean * scale;
    }
    if (RESID2 && tid < K) {
        float mean = SR[tid] / (float)M;
        float var = QR[tid] / (float)M - mean * mean;
        float scale = gR[tid] * rsqrtf(var + EPSV);
        rSc[tid] = scale;
        rSh[tid] = beR[tid] - mean * scale;
    }
    if (FUSEA || RESID2) __syncthreads();

    for (int k0 = 0; k0 < K; k0 += 16) {
        #pragma unroll
        for (int l = 0; l < 2; l++) {
            int f = tid + l * 256;
            int r = f >> 2, c = (f & 3) * 4;
            int gr = rowBase + r;
            float4 v = make_float4(0.f, 0.f, 0.f, 0.f);
            if (gr < M) {
                v = *(const float4*)(A + (size_t)gr * K + k0 + c);
                if (FUSEA) {
                    int kc = k0 + c;
                    v.x = fmaxf(fmaf(v.x, aSc[kc + 0], aSh[kc + 0]), 0.f);
                    v.y = fmaxf(fmaf(v.y, aSc[kc + 1], aSh[kc + 1]), 0.f);
                    v.z = fmaxf(fmaf(v.z, aSc[kc + 2], aSh[kc + 2]), 0.f);
                    v.w = fmaxf(fmaf(v.w, aSc[kc + 3], aSh[kc + 3]), 0.f);
                }
                if (RESID2) {
                    int kc = k0 + c;
                    float4 rr = *(const float4*)(R + (size_t)gr * K + k0 + c);
                    v.x += fmaxf(fmaf(rr.x, rSc[kc + 0], rSh[kc + 0]), 0.f);
                    v.y += fmaxf(fmaf(rr.y, rSc[kc + 1], rSh[kc + 1]), 0.f);
                    v.z += fmaxf(fmaf(rr.z, rSc[kc + 2], rSh[kc + 2]), 0.f);
                    v.w += fmaxf(fmaf(rr.w, rSc[kc + 3], rSh[kc + 3]), 0.f);
                }
            }
            As[r][c] = v.x; As[r][c + 1] = v.y; As[r][c + 2] = v.z; As[r][c + 3] = v.w;
        }
        {
            int r = tid >> 4, c = (tid & 15) * 4;
            int gc = colBase + c;
            float4 v = make_float4(0.f, 0.f, 0.f, 0.f);
            if (gc < Nc) v = *(const float4*)(B + (size_t)(k0 + r) * Nc + gc);
            Bs[r][c] = v.x; Bs[r][c + 1] = v.y; Bs[r][c + 2] = v.z; Bs[r][c + 3] = v.w;
        }
        __syncthreads();
        #pragma unroll
        for (int kk = 0; kk < 16; kk++) {
            float4 bv = *(const float4*)&Bs[kk][tx * 4];
            float a[8];
            #pragma unroll
            for (int i = 0; i < 8; i++) a[i] = As[ty * 8 + i][kk];
            #pragma unroll
            for (int i = 0; i < 8; i++) {
                acc[i][0] = fmaf(a[i], bv.x, acc[i][0]);
                acc[i][1] = fmaf(a[i], bv.y, acc[i][1]);
                acc[i][2] = fmaf(a[i], bv.z, acc[i][2]);
                acc[i][3] = fmaf(a[i], bv.w, acc[i][3]);
            }
        }
        __syncthreads();
    }
    float w10 = DUAL ? g_w[KHOPS] : 0.f;
    #pragma unroll
    for (int i = 0; i < 8; i++) {
        int r = rowBase + ty * 8 + i;
        if (r >= M) continue;
        #pragma unroll
        for (int j = 0; j < 4; j++) {
            int c = colBase + tx * 4 + j;
            if (c < Nc) {
                float v = acc[i][j];
                C[(size_t)r * Nc + c] = v;
                if (DUAL) C2[(size_t)r * Nc + c] = w10 * v;
            }
        }
    }
    if (STATS) {
        float s[4] = {0.f, 0.f, 0.f, 0.f};
        float q[4] = {0.f, 0.f, 0.f, 0.f};
        #pragma unroll
        for (int i = 0; i < 8; i++) {
            int r = rowBase + ty * 8 + i;
            if (r >= M) continue;
            #pragma unroll
            for (int j = 0; j < 4; j++) {
                float v = acc[i][j];
                s[j] += v; q[j] += v * v;
            }
        }
        #pragma unroll
        for (int j = 0; j < 4; j++) {
            atomicAdd(&cS[tx * 4 + j], s[j]);
            atomicAdd(&cQ[tx * 4 + j], q[j]);
        }
        __syncthreads();
        if (tid < 64) {
            int c = colBase + tid;
            if (c < Nc) {
                atomicAdd(Sp + c, cS[tid]);
                atomicAdd(Qp + c, cQ[tid]);
            }
        }
    }
}

// ---------------- tf32 helpers -----------------------------------------------
__device__ __forceinline__ uint32_t f2tf32(float f) {
    uint32_t r;
    asm("cvt.rna.tf32.f32 %0, %1;" : "=r"(r) : "f"(f));
    return r;
}
__device__ __forceinline__ void mma_tf32(float* c, const uint32_t* a, const uint32_t* b) {
    asm("mma.sync.aligned.m16n8k8.row.col.f32.tf32.tf32.f32 "
        "{%0,%1,%2,%3}, {%4,%5,%6,%7}, {%8,%9}, {%0,%1,%2,%3};"
        : "+f"(c[0]), "+f"(c[1]), "+f"(c[2]), "+f"(c[3])
        : "r"(a[0]), "r"(a[1]), "r"(a[2]), "r"(a[3]), "r"(b[0]), "r"(b[1]));
}

// ---------------- tf32 tensor-core output GEMM (1x, K=64) --------------------
// C[M,Nc] = relu(bn(A)) @ B + bias. BM=BN=128, 8 warps (2x4), 64x32 warp tile.
__global__ __launch_bounds__(256, 2)
void k_gemm_tc(const float* __restrict__ A, const float* __restrict__ B,
               const float* __restrict__ bias, float* __restrict__ C,
               const float* __restrict__ gA, const float* __restrict__ beA,
               const float* __restrict__ SA, const float* __restrict__ QA,
               int M, int Nc) {
    __shared__ float As[128][68];
    __shared__ float Bs[64][132];
    __shared__ float aSc[HD2], aSh[HD2];
    int tid = threadIdx.x;
    int rowBase = blockIdx.y * 128;
    int colBase = blockIdx.x * 128;

    if (tid < HD2) {
        float mean = SA[tid] / (float)M;
        float var = QA[tid] / (float)M - mean * mean;
        float scale = gA[tid] * rsqrtf(var + EPSV);
        aSc[tid] = scale;
        aSh[tid] = beA[tid] - mean * scale;
    }
    __syncthreads();

    #pragma unroll
    for (int l = 0; l < 8; l++) {
        int f = tid + l * 256;
        int r = f >> 4;
        int c = (f & 15) * 4;
        int gr = rowBase + r;
        float4 v = make_float4(0.f, 0.f, 0.f, 0.f);
        if (gr < M) {
            v = *(const float4*)(A + (size_t)gr * HD2 + c);
            v.x = fmaxf(fmaf(v.x, aSc[c + 0], aSh[c + 0]), 0.f);
            v.y = fmaxf(fmaf(v.y, aSc[c + 1], aSh[c + 1]), 0.f);
            v.z = fmaxf(fmaf(v.z, aSc[c + 2], aSh[c + 2]), 0.f);
            v.w = fmaxf(fmaf(v.w, aSc[c + 3], aSh[c + 3]), 0.f);
        }
        As[r][c] = v.x; As[r][c + 1] = v.y; As[r][c + 2] = v.z; As[r][c + 3] = v.w;
    }
    #pragma unroll
    for (int l = 0; l < 8; l++) {
        int f = tid + l * 256;
        int r = f >> 5;
        int c = (f & 31) * 4;
        int gc = colBase + c;
        float4 v = make_float4(0.f, 0.f, 0.f, 0.f);
        if (gc + 3 < Nc) v = *(const float4*)(B + (size_t)r * Nc + gc);
        Bs[r][c] = v.x; Bs[r][c + 1] = v.y; Bs[r][c + 2] = v.z; Bs[r][c + 3] = v.w;
    }
    __syncthreads();

    int warpId = tid >> 5;
    int lane = tid & 31;
    int g = lane >> 2;
    int t = lane & 3;
    int rowOff = (warpId >> 2) * 64;
    int colOff = (warpId & 3) * 32;

    float cacc[4][4][4] = {};

    #pragma unroll
    for (int ks = 0; ks < 8; ks++) {
        int kb = ks * 8;
        uint32_t af[4][4];
        #pragma unroll
        for (int mt = 0; mt < 4; mt++) {
            int r0 = rowOff + mt * 16 + g;
            af[mt][0] = f2tf32(As[r0][kb + t]);
            af[mt][1] = f2tf32(As[r0 + 8][kb + t]);
            af[mt][2] = f2tf32(As[r0][kb + t + 4]);
            af[mt][3] = f2tf32(As[r0 + 8][kb + t + 4]);
        }
        uint32_t bf[4][2];
        #pragma unroll
        for (int nt = 0; nt < 4; nt++) {
            int c0 = colOff + nt * 8 + g;
            bf[nt][0] = f2tf32(Bs[kb + t][c0]);
            bf[nt][1] = f2tf32(Bs[kb + t + 4][c0]);
        }
        #pragma unroll
        for (int mt = 0; mt < 4; mt++)
            #pragma unroll
            for (int nt = 0; nt < 4; nt++)
                mma_tf32(cacc[mt][nt], af[mt], bf[nt]);
    }

    #pragma unroll
    for (int mt = 0; mt < 4; mt++) {
        int row0 = rowBase + rowOff + mt * 16 + g;
        int row1 = row0 + 8;
        #pragma unroll
        for (int nt = 0; nt < 4; nt++) {
            int col = colBase + colOff + nt * 8 + 2 * t;
            const float* cc = cacc[mt][nt];
            if (row0 < M) {
                if (col < Nc)     C[(size_t)row0 * Nc + col]     = cc[0] + bias[col];
                if (col + 1 < Nc) C[(size_t)row0 * Nc + col + 1] = cc[1] + bias[col + 1];
            }
            if (row1 < M) {
                if (col < Nc)     C[(size_t)row1 * Nc + col]     = cc[2] + bias[col];
                if (col + 1 < Nc) C[(size_t)row1 * Nc + col + 1] = cc[3] + bias[col + 1];
            }
        }
    }
}

// ---------------- CSR build: histogram -> scan -> scatter --------------------
__global__ void k_hist(const int* __restrict__ dst) {
    int t = blockIdx.x * blockDim.x + threadIdx.x;
    int stride = gridDim.x * blockDim.x;
    for (int e = t; e < EE; e += stride) atomicAdd(&g_deg[dst[e]], 1);
}

__global__ void k_scan() {  // one block, 1024 threads
    __shared__ int ss[1024];
    int t = threadIdx.x;
    const int CH = (NN + 1023) / 1024;
    int lo = t * CH;
    int hi = lo + CH; if (hi > NN) hi = NN;
    int loc = 0;
    for (int i = lo; i < hi; i++) loc += g_deg[i];
    ss[t] = loc;
    __syncthreads();
    for (int off = 1; off < 1024; off <<= 1) {
        int v = (t >= off) ? ss[t - off] : 0;
        __syncthreads();
        ss[t] += v;
        __syncthreads();
    }
    int run = ss[t] - loc;  // exclusive prefix
    for (int i = lo; i < hi; i++) {
        g_rowptr[i] = run;
        g_cursor[i] = run;
        run += g_deg[i];
    }
    if (t == 1023) g_rowptr[NN] = ss[1023];
}

__global__ void k_scatter(const int* __restrict__ src, const int* __restrict__ dst) {
    int t = blockIdx.x * blockDim.x + threadIdx.x;
    int stride = gridDim.x * blockDim.x;
    for (int e = t; e < EE; e += stride) {
        int d = dst[e];
        int p = atomicAdd(&g_cursor[d], 1);
        g_colidx[p] = src[e];
    }
}

// ---------------- Horner propagation step ------------------------------------
// nxt[d] = w[k]*P[d] + sum_{in-edges} cur[src].  LAST step also accumulates
// BN3 column stats (S3/Q3) via shfl-fold + smem + global atomics.
// Grid is exactly NN*16/256 = 3125 blocks: every thread owns a valid dst.
template<bool LAST>
__global__ __launch_bounds__(256)
void k_hopH(const float* __restrict__ cur, float* __restrict__ nxt, int k) {
    __shared__ float sS[64], sQ[64];
    int tid = threadIdx.x;
    if (LAST) {
        if (tid < 64) { sS[tid] = 0.f; sQ[tid] = 0.f; }
        __syncthreads();
    }
    int gid = blockIdx.x * 256 + tid;
    int d = gid >> 4;            // half-warp per destination node
    int lane = tid & 15;
    float wk = g_w[k];
    int s = g_rowptr[d];
    int e = g_rowptr[d + 1];
    float4 acc0 = make_float4(0.f, 0.f, 0.f, 0.f);
    float4 acc1 = make_float4(0.f, 0.f, 0.f, 0.f);
    float4 acc2 = make_float4(0.f, 0.f, 0.f, 0.f);
    float4 acc3 = make_float4(0.f, 0.f, 0.f, 0.f);
    int i = s;
    for (; i + 3 < e; i += 4) {
        int s0 = __ldg(&g_colidx[i]);
        int s1 = __ldg(&g_colidx[i + 1]);
        int s2 = __ldg(&g_colidx[i + 2]);
        int s3 = __ldg(&g_colidx[i + 3]);
        float4 v0 = *(const float4*)(cur + (size_t)s0 * HD2 + lane * 4);
        float4 v1 = *(const float4*)(cur + (size_t)s1 * HD2 + lane * 4);
        float4 v2 = *(const float4*)(cur + (size_t)s2 * HD2 + lane * 4);
        float4 v3 = *(const float4*)(cur + (size_t)s3 * HD2 + lane * 4);
        acc0.x += v0.x; acc0.y += v0.y; acc0.z += v0.z; acc0.w += v0.w;
        acc1.x += v1.x; acc1.y += v1.y; acc1.z += v1.z; acc1.w += v1.w;
        acc2.x += v2.x; acc2.y += v2.y; acc2.z += v2.z; acc2.w += v2.w;
        acc3.x += v3.x; acc3.y += v3.y; acc3.z += v3.z; acc3.w += v3.w;
    }
    for (; i < e; i++) {
        int s0 = __ldg(&g_colidx[i]);
        float4 v0 = *(const float4*)(cur + (size_t)s0 * HD2 + lane * 4);
        acc0.x += v0.x; acc0.y += v0.y; acc0.z += v0.z; acc0.w += v0.w;
    }
    float4 a = make_float4((acc0.x + acc1.x) + (acc2.x + acc3.x),
                           (acc0.y + acc1.y) + (acc2.y + acc3.y),
                           (acc0.z + acc1.z) + (acc2.z + acc3.z),
                           (acc0.w + acc1.w) + (acc2.w + acc3.w));
    size_t base = (size_t)d * HD2 + lane * 4;
    float4 p = *(const float4*)(g_P + base);
    float4 q;
    q.x = fmaf(wk, p.x, a.x);
    q.y = fmaf(wk, p.y, a.y);
    q.z = fmaf(wk, p.z, a.z);
    q.w = fmaf(wk, p.w, a.w);
    *(float4*)(nxt + base) = q;

    if (LAST) {
        float s0 = q.x, s1 = q.y, s2 = q.z, s3 = q.w;
        float q0 = q.x * q.x, q1 = q.y * q.y, q2 = q.z * q.z, q3 = q.w * q.w;
        s0 += __shfl_xor_sync(0xFFFFFFFF, s0, 16);
        s1 += __shfl_xor_sync(0xFFFFFFFF, s1, 16);
        s2 += __shfl_xor_sync(0xFFFFFFFF, s2, 16);
        s3 += __shfl_xor_sync(0xFFFFFFFF, s3, 16);
        q0 += __shfl_xor_sync(0xFFFFFFFF, q0, 16);
        q1 += __shfl_xor_sync(0xFFFFFFFF, q1, 16);
        q2 += __shfl_xor_sync(0xFFFFFFFF, q2, 16);
        q3 += __shfl_xor_sync(0xFFFFFFFF, q3, 16);
        if ((tid & 31) < 16) {
            int c0 = lane * 4;
            atomicAdd(&sS[c0 + 0], s0); atomicAdd(&sQ[c0 + 0], q0);
            atomicAdd(&sS[c0 + 1], s1); atomicAdd(&sQ[c0 + 1], q1);
            atomicAdd(&sS[c0 + 2], s2); atomicAdd(&sQ[c0 + 2], q2);
            atomicAdd(&sS[c0 + 3], s3); atomicAdd(&sQ[c0 + 3], q3);
        }
        __syncthreads();
        if (tid < 64) {
            atomicAdd(g_S3 + tid, sS[tid]);
            atomicAdd(g_Q3 + tid, sQ[tid]);
        }
    }
}

// ---------------- host launcher ----------------------------------------------
extern "C" void kernel_launch(void* const* d_in, const int* in_sizes, int n_in,
                              void* d_out, int out_size) {
    const float* x    = (const float*)d_in[0];
    const int*   ei   = (const int*)d_in[1];
    const float* W1   = (const float*)d_in[2];
    const float* g1   = (const float*)d_in[4];
    const float* be1  = (const float*)d_in[5];
    const float* W2   = (const float*)d_in[6];
    const float* g2   = (const float*)d_in[8];
    const float* be2  = (const float*)d_in[9];
    const float* att  = (const float*)d_in[10];
    const float* W3   = (const float*)d_in[11];
    const float* g3   = (const float*)d_in[13];
    const float* be3  = (const float*)d_in[14];
    const float* Wout = (const float*)d_in[15];
    const float* bout = (const float*)d_in[16];
    const int* srcp = ei;
    const int* dstp = ei + EE;
    float* out = (float*)d_out;

    float *Y1, *Y2, *P, *PB, *QB, *S1, *Q1, *S2, *Q2, *S3, *Q3;
    cudaGetSymbolAddress((void**)&Y1, g_Y1);
    cudaGetSymbolAddress((void**)&Y2, g_Y2);
    cudaGetSymbolAddress((void**)&P,  g_P);
    cudaGetSymbolAddress((void**)&PB, g_PB);
    cudaGetSymbolAddress((void**)&QB, g_QB);
    cudaGetSymbolAddress((void**)&S1, g_S1);
    cudaGetSymbolAddress((void**)&Q1, g_Q1);
    cudaGetSymbolAddress((void**)&S2, g_S2);
    cudaGetSymbolAddress((void**)&Q2, g_Q2);
    cudaGetSymbolAddress((void**)&S3, g_S3);
    cudaGetSymbolAddress((void**)&Q3, g_Q3);

    const int MB = (NN + 127) / 128;      // 391 row-tiles
    const int HOPBLOCKS = NN * 16 / 256;  // 3125 exactly

    // fork/join plumbing for overlapping the CSR build with the MLP GEMMs.
    cudaStream_t s2;
    cudaEvent_t evFork, evJoin;
    cudaStreamCreateWithFlags(&s2, cudaStreamNonBlocking);
    cudaEventCreateWithFlags(&evFork, cudaEventDisableTiming);
    cudaEventCreateWithFlags(&evJoin, cudaEventDisableTiming);

    k_init<<<200, 256>>>(att);

    // fork: CSR build runs on s2 concurrently with the MLP GEMMs on stream 0
    cudaEventRecord(evFork, 0);
    cudaStreamWaitEvent(s2, evFork, 0);
    k_hist<<<1024, 256, 0, s2>>>(dstp);
    k_scan<<<1, 1024, 0, s2>>>();
    k_scatter<<<1024, 256, 0, s2>>>(srcp, dstp);
    cudaEventRecord(evJoin, s2);

    // layer 1: Y1 = x @ W1 (stats fused), FFMA
    k_gemm<false, false, true, false><<<dim3(2, MB), 256>>>(
        x, W1, Y1, nullptr, S1, Q1,
        nullptr, nullptr, nullptr, nullptr,
        nullptr, nullptr, nullptr, nullptr, nullptr, NN, HD, IN_DIM);

    // layer 2: Y2 = relu(bn1(Y1)) @ W2 (apply fused on A; stats fused), FFMA
    k_gemm<true, false, true, false><<<dim3(2, MB), 256>>>(
        Y1, W2, Y2, nullptr, S2, Q2,
        g1, be1, S1, Q1,
        nullptr, nullptr, nullptr, nullptr, nullptr, NN, HD, HD);

    // projection: P = (relu(bn2(Y2)) + relu(bn1(Y1))) @ W3;  PB = w10 * P (Horner seed)
    k_gemm<true, true, false, true><<<dim3(1, MB), 256>>>(
        Y2, W3, P, PB, nullptr, nullptr,
        g2, be2, S2, Q2,
        Y1, g1, be1, S1, Q1, NN, HD2, HD);

    // join: hops need the CSR
    cudaStreamWaitEvent(0, evJoin, 0);

    // Horner: t_k = w_k*P + A*t_{k+1}, k = 9..0; t10 = PB; final lands in PB.
    {
        float* cur = PB;
        float* nxt = QB;
        for (int k = KHOPS - 1; k >= 1; k--) {
            k_hopH<false><<<HOPBLOCKS, 256>>>(cur, nxt, k);
            float* tmp = cur; cur = nxt; nxt = tmp;
        }
        k_hopH<true><<<HOPBLOCKS, 256>>>(cur, nxt, 0);  // nxt == PB, stats fused
    }

    // output: out = relu(bn3(t0)) @ Wout + bout   [1x tf32 tensor cores]
    k_gemm_tc<<<dim3((OUT_DIM + 127) / 128, MB), 256>>>(
        PB, Wout, bout, out, g3, be3, S3, Q3, NN, OUT_DIM);
}